// round 12
// baseline (speedup 1.0000x reference)
#include <cuda_runtime.h>
#include <cuda_bf16.h>
#include <math.h>
#include <cstdint>

// Shape fixed by dataset: B=16, N=1024, E=128, kv row = 2E+1 = 257
#define BATCH   16
#define NATOMS  1024
#define EDIM    128
#define KVROW   257
#define TI      128
#define TJ      64
#define NTILES  16
#define THREADS 512

// Pre-split bf16 operands, packed 2 per uint32: [b][n][pair] (64 pairs/row)
__device__ uint32_t g_khi[BATCH * NATOMS * 64];
__device__ uint32_t g_klo[BATCH * NATOMS * 64];
__device__ uint32_t g_vhi[BATCH * NATOMS * 64];
__device__ uint32_t g_vlo[BATCH * NATOMS * 64];

// Operand rows padded to 272 B (ldmatrix conflict-free without swizzle).
#define STRIDE_B 272
// S tile: 128 rows x 64 cols fp32, stride 72 floats, col-halves offset 36
// -> conflict-free STS.64 (producers) and LDS.128 (consumers).
#define S_STRIDE 72

#define OFF_AHI  0                       // 128*272 = 34816
#define OFF_ALO  34816
#define OFF_B0HI 69632                   // 64*272 = 17408 each
#define OFF_B0LO 87040
#define OFF_B1HI 104448
#define OFF_B1LO 121856
#define OFF_S0   139264                  // 128*72*4 = 36864 each
#define OFF_S1   176128
#define OFF_POS  212992                  // 2 stages x 64 cols x 16B
#define OFF_MS   215040                  // 16 floats
#define SMEM_BYTES 215296

__device__ __forceinline__ uint32_t smem_u32(const void* p) {
    uint32_t a;
    asm("{ .reg .u64 t; cvta.to.shared.u64 t, %1; cvt.u32.u64 %0, t; }"
        : "=r"(a) : "l"(p));
    return a;
}
__device__ __forceinline__ void cpa16(uint32_t dst, const void* src) {
    asm volatile("cp.async.cg.shared.global [%0], [%1], 16;" :: "r"(dst), "l"(src));
}
#define CP_COMMIT() asm volatile("cp.async.commit_group;" ::: "memory")
#define CP_WAIT0()  asm volatile("cp.async.wait_group 0;" ::: "memory")

#define BAR_SYNC(id, cnt)   asm volatile("bar.sync %0, %1;"   :: "r"(id), "r"(cnt) : "memory")
#define BAR_ARRIVE(id, cnt) asm volatile("bar.arrive %0, %1;" :: "r"(id), "r"(cnt) : "memory")
// barrier ids: 2/3 = S0/S1 full (512), 4/5 = S0/S1 free (512),
//              6 = producers-only (256), 7 = consumers-only (256)

#define LDSM4(r, addr)                                                      \
    asm volatile("ldmatrix.sync.aligned.m8n8.x4.shared.b16 {%0,%1,%2,%3}, [%4];" \
        : "=r"((r)[0]), "=r"((r)[1]), "=r"((r)[2]), "=r"((r)[3]) : "r"(addr))

#define MMA_BF16(c, a, b0_, b1_)                                            \
    asm volatile("mma.sync.aligned.m16n8k16.row.col.f32.bf16.bf16.f32 "     \
        "{%0,%1,%2,%3}, {%4,%5,%6,%7}, {%8,%9}, {%0,%1,%2,%3};"             \
        : "+f"((c)[0]), "+f"((c)[1]), "+f"((c)[2]), "+f"((c)[3])            \
        : "r"((a)[0]), "r"((a)[1]), "r"((a)[2]), "r"((a)[3]),               \
          "r"(b0_), "r"(b1_))

// ---------------- prepass: fp32 -> bf16 hi/lo split, packed pairs ----------
__global__ __launch_bounds__(256)
void split_kv_kernel(const float* __restrict__ kv,
                     const float* __restrict__ mask)
{
    int idx = blockIdx.x * 256 + threadIdx.x;        // [0, B*N*64)
    if (idx >= BATCH * NATOMS * 64) return;
    int p = idx & 63;
    int n = (idx >> 6) & (NATOMS - 1);
    int b = idx >> 16;

    const float* row = kv + ((size_t)b * NATOMS + n) * KVROW;
    float m  = mask[b * NATOMS + n];
    float mk = m * 0.088388347648318447f;            // mask * 1/sqrt(128)

    float k0 = row[2 * p] * mk,        k1 = row[2 * p + 1] * mk;
    float v0 = row[EDIM + 2 * p] * m,  v1 = row[EDIM + 2 * p + 1] * m;

    __nv_bfloat16 kh0 = __float2bfloat16(k0), kh1 = __float2bfloat16(k1);
    __nv_bfloat16 kl0 = __float2bfloat16(k0 - __bfloat162float(kh0));
    __nv_bfloat16 kl1 = __float2bfloat16(k1 - __bfloat162float(kh1));
    __nv_bfloat16 vh0 = __float2bfloat16(v0), vh1 = __float2bfloat16(v1);
    __nv_bfloat16 vl0 = __float2bfloat16(v0 - __bfloat162float(vh0));
    __nv_bfloat16 vl1 = __float2bfloat16(v1 - __bfloat162float(vh1));

    g_khi[idx] = (uint32_t)__bfloat16_as_ushort(kh0) | ((uint32_t)__bfloat16_as_ushort(kh1) << 16);
    g_klo[idx] = (uint32_t)__bfloat16_as_ushort(kl0) | ((uint32_t)__bfloat16_as_ushort(kl1) << 16);
    g_vhi[idx] = (uint32_t)__bfloat16_as_ushort(vh0) | ((uint32_t)__bfloat16_as_ushort(vh1) << 16);
    g_vlo[idx] = (uint32_t)__bfloat16_as_ushort(vl0) | ((uint32_t)__bfloat16_as_ushort(vl1) << 16);
}

struct Frags {
    uint32_t ah[2][4], al[2][4], bh[2][4], bl[2][4];
};

__device__ __forceinline__ void load_frags(Frags& f, int kc,
    uint32_t aHiB, uint32_t aLoB, uint32_t bHiB, uint32_t bLoB)
{
    uint32_t ko = kc * 32;
    #pragma unroll
    for (int mt = 0; mt < 2; mt++) {
        uint32_t o = mt * (16 * STRIDE_B) + ko;
        LDSM4(f.ah[mt], aHiB + o);
        LDSM4(f.al[mt], aLoB + o);
    }
    #pragma unroll
    for (int ng = 0; ng < 2; ng++) {
        uint32_t o = ng * (16 * STRIDE_B) + ko;
        LDSM4(f.bh[ng], bHiB + o);
        LDSM4(f.bl[ng], bLoB + o);
    }
}

__device__ __forceinline__ void mma_frags(float (&C)[2][4][4], const Frags& f)
{
    #pragma unroll
    for (int mt = 0; mt < 2; mt++)
        #pragma unroll
        for (int ng = 0; ng < 2; ng++) {
            MMA_BF16(C[mt][2 * ng],     f.ah[mt], f.bh[ng][0], f.bh[ng][1]);
            MMA_BF16(C[mt][2 * ng + 1], f.ah[mt], f.bh[ng][2], f.bh[ng][3]);
        }
    #pragma unroll
    for (int mt = 0; mt < 2; mt++)
        #pragma unroll
        for (int ng = 0; ng < 2; ng++) {
            MMA_BF16(C[mt][2 * ng],     f.ah[mt], f.bl[ng][0], f.bl[ng][1]);
            MMA_BF16(C[mt][2 * ng + 1], f.ah[mt], f.bl[ng][2], f.bl[ng][3]);
        }
    #pragma unroll
    for (int mt = 0; mt < 2; mt++)
        #pragma unroll
        for (int ng = 0; ng < 2; ng++) {
            MMA_BF16(C[mt][2 * ng],     f.al[mt], f.bh[ng][0], f.bh[ng][1]);
            MMA_BF16(C[mt][2 * ng + 1], f.al[mt], f.bh[ng][2], f.bh[ng][3]);
        }
}

// ---------------- main kernel: 8 producer warps + 8 consumer warps ---------
__global__ __launch_bounds__(THREADS, 1)
void gen_actions_kernel(const float* __restrict__ pos,
                        const float* __restrict__ mask,
                        const float* __restrict__ ascale,
                        float* __restrict__ out)
{
    extern __shared__ char sp[];
    const uint32_t sb = smem_u32(sp);
    float* sS0 = (float*)(sp + OFF_S0);
    float* sS1 = (float*)(sp + OFF_S1);

    const int tid  = threadIdx.x;
    const int wid  = tid >> 5;
    const int lane = tid & 31;
    const int b  = blockIdx.y;
    const int i0 = blockIdx.x * TI;

    const float* mb = mask + (size_t)b * NATOMS;
    const float* pb = pos  + (size_t)b * NATOMS * 3;

    if (wid < 8) {
        // ================= PRODUCER =================
        const int pwr = wid & 3;        // rows [32pwr, 32pwr+32)
        const int pwc = wid >> 2;       // cols [32pwc, 32pwc+32)
        const int qid = lane >> 2;
        const int qe  = lane & 3;

        // prologue: A (hi+lo) + B tile 0 (hi+lo), one cp group
        {
            const uint32_t* ah = g_khi + ((size_t)b * NATOMS + i0) * 64;
            const uint32_t* al = g_klo + ((size_t)b * NATOMS + i0) * 64;
            #pragma unroll
            for (int it = 0; it < 8; it++) {
                int idx = tid + it * 256;            // [0,2048)
                int r = idx >> 4, c = idx & 15;
                cpa16(sb + OFF_AHI + r * STRIDE_B + c * 16, ah + r * 64 + c * 4);
                cpa16(sb + OFF_ALO + r * STRIDE_B + c * 16, al + r * 64 + c * 4);
            }
            const uint32_t* bh = g_vhi + (size_t)b * NATOMS * 64;
            const uint32_t* bl = g_vlo + (size_t)b * NATOMS * 64;
            #pragma unroll
            for (int it = 0; it < 4; it++) {
                int idx = tid + it * 256;            // [0,1024)
                int r = idx >> 4, c = idx & 15;
                cpa16(sb + OFF_B0HI + r * STRIDE_B + c * 16, bh + r * 64 + c * 4);
                cpa16(sb + OFF_B0LO + r * STRIDE_B + c * 16, bl + r * 64 + c * 4);
            }
            CP_COMMIT();
        }

        const uint32_t aRow = 32 * pwr + (lane & 15);
        const uint32_t aKof = (lane & 16) ? 16u : 0u;
        const uint32_t aHiB = sb + OFF_AHI + aRow * STRIDE_B + aKof;
        const uint32_t aLoB = sb + OFF_ALO + aRow * STRIDE_B + aKof;
        const uint32_t bRow = 32 * pwc + (lane & 7) + ((lane & 16) ? 8 : 0);
        const uint32_t bKof = (lane & 8) ? 16u : 0u;
        const uint32_t bLaneOff = bRow * STRIDE_B + bKof;

        for (int t = 0; t < NTILES; t++) {
            CP_WAIT0();                 // B(t) landed (this thread's groups)
            BAR_SYNC(6, 256);           // all producers' loads visible

            if (t + 1 < NTILES) {       // refill B(t+1) into other stage
                const int jn = (t + 1) * TJ;
                const uint32_t hiN = ((t + 1) & 1) ? OFF_B1HI : OFF_B0HI;
                const uint32_t loN = ((t + 1) & 1) ? OFF_B1LO : OFF_B0LO;
                const uint32_t* bh = g_vhi + ((size_t)b * NATOMS + jn) * 64;
                const uint32_t* bl = g_vlo + ((size_t)b * NATOMS + jn) * 64;
                #pragma unroll
                for (int it = 0; it < 4; it++) {
                    int idx = tid + it * 256;
                    int r = idx >> 4, c = idx & 15;
                    cpa16(sb + hiN + r * STRIDE_B + c * 16, bh + r * 64 + c * 4);
                    cpa16(sb + loN + r * STRIDE_B + c * 16, bl + r * 64 + c * 4);
                }
                CP_COMMIT();
            }

            if (t >= 2) BAR_SYNC(4 + (t & 1), 512);   // S[t&1] free

            const uint32_t bHiB = sb + ((t & 1) ? OFF_B1HI : OFF_B0HI) + bLaneOff;
            const uint32_t bLoB = sb + ((t & 1) ? OFF_B1LO : OFF_B0LO) + bLaneOff;

            float C[2][4][4];
            #pragma unroll
            for (int mt = 0; mt < 2; mt++)
                #pragma unroll
                for (int nt = 0; nt < 4; nt++)
                    #pragma unroll
                    for (int e = 0; e < 4; e++) C[mt][nt][e] = 0.f;

            Frags fr[2];
            load_frags(fr[0], 0, aHiB, aLoB, bHiB, bLoB);
            #pragma unroll
            for (int kc = 0; kc < 8; kc++) {
                if (kc < 7)
                    load_frags(fr[(kc + 1) & 1], kc + 1, aHiB, aLoB, bHiB, bLoB);
                mma_frags(C, fr[kc & 1]);
            }

            // write S tile (stride 72, halves at 0/36) — conflict-free STS.64
            float* sS = (t & 1) ? sS1 : sS0;
            #pragma unroll
            for (int mt = 0; mt < 2; mt++)
                #pragma unroll
                for (int h = 0; h < 2; h++) {
                    int grow = 32 * pwr + 16 * mt + 8 * h + qid;
                    #pragma unroll
                    for (int nt = 0; nt < 4; nt++) {
                        int fidx = grow * S_STRIDE + 36 * pwc + 8 * nt + 2 * qe;
                        float2 v2 = make_float2(C[mt][nt][2 * h], C[mt][nt][2 * h + 1]);
                        *(float2*)&sS[fidx] = v2;
                    }
                }
            __threadfence_block();
            BAR_ARRIVE(2 + (t & 1), 512);             // S[t&1] full
        }
        // producers exit; no further barrier participation required
    } else {
        // ================= CONSUMER =================
        const int ctid = tid - 256;                   // 0..255
        const int cw   = wid - 8;                     // 0..7
        const int row  = 16 * cw + (lane >> 1);       // this thread's S row
        const int hf   = lane & 1;                    // column half (0/32)

        // pos tile 0 into stage 0 (padded float4)
        if (ctid < TJ) {
            const float* p = pb + (size_t)ctid * 3;
            float4 q = make_float4(p[0], p[1], p[2], 0.f);
            *(float4*)(sp + OFF_POS + ctid * 16) = q;
        }
        // mask sum (consumers only)
        float* sMS = (float*)(sp + OFF_MS);
        {
            float ms = 0.f;
            for (int n = ctid; n < NATOMS; n += 256) ms += mb[n];
            #pragma unroll
            for (int off = 16; off > 0; off >>= 1)
                ms += __shfl_xor_sync(0xFFFFFFFFu, ms, off);
            if (lane == 0) sMS[cw] = ms;
        }
        BAR_SYNC(7, 256);
        float msum = 0.f;
        #pragma unroll
        for (int q = 0; q < 8; q++) msum += sMS[q];
        const float inv_msum = 1.0f / msum;
        const float as = ascale[0];

        const int gi = i0 + row;
        const float pix = pb[(size_t)gi * 3 + 0];
        const float piy = pb[(size_t)gi * 3 + 1];
        const float piz = pb[(size_t)gi * 3 + 2];

        float ax = 0.f, ay = 0.f, az = 0.f;

        for (int t = 0; t < NTILES; t++) {
            // early global read of next pos tile
            float nx = 0.f, ny = 0.f, nz = 0.f;
            if (t + 1 < NTILES && ctid < TJ) {
                const float* p = pb + (size_t)((t + 1) * TJ + ctid) * 3;
                nx = p[0]; ny = p[1]; nz = p[2];
            }

            BAR_SYNC(2 + (t & 1), 512);               // S(t) full

            if (t + 1 < NTILES && ctid < TJ)          // stage (t+1)&1
                *(float4*)(sp + OFF_POS + ((t + 1) & 1) * 1024 + ctid * 16)
                    = make_float4(nx, ny, nz, 0.f);

            const float* sS = (t & 1) ? sS1 : sS0;
            const float4* sQ = (const float4*)(sp + OFF_POS + (t & 1) * 1024);
            const int base = row * S_STRIDE + 36 * hf;

            #pragma unroll
            for (int c4 = 0; c4 < 8; c4++) {
                float4 s4 = *(const float4*)&sS[base + 4 * c4];
                float sv[4] = { s4.x, s4.y, s4.z, s4.w };
                #pragma unroll
                for (int e = 0; e < 4; e++) {
                    float4 q = sQ[32 * hf + 4 * c4 + e];
                    float dx = pix - q.x;
                    float dy = piy - q.y;
                    float dz = piz - q.z;
                    float d2 = fmaf(dx, dx, fmaf(dy, dy, dz * dz));
                    float inv = rsqrtf(fmaxf(d2, 1e-36f));   // diag -> 0
                    float w = sv[e] * inv;
                    ax = fmaf(w, dx, ax);
                    ay = fmaf(w, dy, ay);
                    az = fmaf(w, dz, az);
                }
            }

            BAR_SYNC(7, 256);                          // pos stage visible
            if (t < NTILES - 2) BAR_ARRIVE(4 + (t & 1), 512);  // S free
        }

        // fold the two column halves (lanes differ in bit 0)
        ax += __shfl_xor_sync(0xFFFFFFFFu, ax, 1);
        ay += __shfl_xor_sync(0xFFFFFFFFu, ay, 1);
        az += __shfl_xor_sync(0xFFFFFFFFu, az, 1);

        if (hf == 0) {
            float s = as * mb[gi];
            float* o = out + ((size_t)b * NATOMS + gi) * 3;
            o[0] = tanhf(ax * inv_msum) * s;
            o[1] = tanhf(ay * inv_msum) * s;
            o[2] = tanhf(az * inv_msum) * s;
        }
    }
}

extern "C" void kernel_launch(void* const* d_in, const int* in_sizes, int n_in,
                              void* d_out, int out_size) {
    const float* kv   = (const float*)d_in[0];
    const float* pos  = (const float*)d_in[1];
    const float* mask = (const float*)d_in[2];
    const float* asc  = (const float*)d_in[3];
    float* out = (float*)d_out;

    cudaFuncSetAttribute(gen_actions_kernel,
                         cudaFuncAttributeMaxDynamicSharedMemorySize,
                         (int)SMEM_BYTES);

    split_kv_kernel<<<(BATCH * NATOMS * 64 + 255) / 256, 256>>>(kv, mask);

    dim3 grid(NATOMS / TI, BATCH);   // 8 x 16 = 128 blocks, one wave
    gen_actions_kernel<<<grid, THREADS, SMEM_BYTES>>>(pos, mask, asc, out);
}